// round 1
// baseline (speedup 1.0000x reference)
#include <cuda_runtime.h>
#include <cstdint>
#include <cstddef>

// Problem constants
constexpr int N_NODES = 8192;
constexpr int C_DIM   = 16;

// Tiling
constexpr int TPB = 256;                 // threads per block
constexpr int CPT = 4;                   // columns per thread
constexpr int CPB = TPB * CPT;           // 1024 columns per block
constexpr int RPB = 128;                 // rows per block
constexpr int GX  = N_NODES / CPB;       // 8
constexpr int GY  = N_NODES / RPB;       // 64
constexpr int NBLK = GX * GY;            // 512

// partials layout per block: [0]=quad, [1]=s, [2..17]=dH[16]
__device__ float g_part[NBLK][18];

__device__ __forceinline__ unsigned long long pack2(float x, float y) {
    unsigned long long r;
    asm("mov.b64 %0, {%1, %2};" : "=l"(r) : "f"(x), "f"(y));
    return r;
}
__device__ __forceinline__ void unpack2(unsigned long long v, float& x, float& y) {
    asm("mov.b64 {%0, %1}, %2;" : "=f"(x), "=f"(y) : "l"(v));
}
// packed fp32x2 FMA (Blackwell sm_10x): d = a*b + c on two lanes
__device__ __forceinline__ unsigned long long fma2(unsigned long long a,
                                                   unsigned long long b,
                                                   unsigned long long c) {
    unsigned long long d;
    asm("fma.rn.f32x2 %0, %1, %2, %3;" : "=l"(d) : "l"(a), "l"(b), "l"(c));
    return d;
}

__global__ void __launch_bounds__(TPB)
modmax_main(const float* __restrict__ A, const float* __restrict__ H) {
    __shared__ __align__(16) float sH[RPB * C_DIM];   // 8 KB: H rows for this chunk

    const int row0 = blockIdx.y * RPB;
    const int col0 = blockIdx.x * CPB + threadIdx.x * CPT;

    // Stage H[row0 : row0+RPB][0:16] into smem (128*16 floats = 512 float4)
    {
        const float4* src = (const float4*)(H + (size_t)row0 * C_DIM);
        float4* dst = (float4*)sH;
        #pragma unroll
        for (int k = threadIdx.x; k < RPB * C_DIM / 4; k += TPB) dst[k] = src[k];
    }
    __syncthreads();

    // Accumulators: w[q] = sum_i adj[i][j_q] * H[i][:]   (8 f32x2 pairs = 16 floats)
    unsigned long long w[CPT][8];
    #pragma unroll
    for (int q = 0; q < CPT; q++)
        #pragma unroll
        for (int c = 0; c < 8; c++) w[q][c] = 0ULL;
    float cnt[CPT] = {0.f, 0.f, 0.f, 0.f};

    const float4* Aeff = (const float4*)(A + (size_t)row0 * N_NODES + col0);
    const size_t rowStride4 = N_NODES / 4;

    // 4-row software pipeline: keep 4 independent LDG.128 in flight
    float4 abuf[4];
    #pragma unroll
    for (int k = 0; k < 4; k++) abuf[k] = __ldg(Aeff + (size_t)k * rowStride4);

    #pragma unroll 1
    for (int i = 0; i < RPB; i += 4) {
        float4 acur[4];
        #pragma unroll
        for (int k = 0; k < 4; k++) acur[k] = abuf[k];
        if (i + 4 < RPB) {
            #pragma unroll
            for (int k = 0; k < 4; k++)
                abuf[k] = __ldg(Aeff + (size_t)(i + 4 + k) * rowStride4);
        }
        #pragma unroll
        for (int k = 0; k < 4; k++) {
            const int ii = i + k;
            // H[ii] as 8 packed f32x2 (broadcast LDS.128 x4, conflict-free)
            const ulonglong2* sh = (const ulonglong2*)(sH + ii * C_DIM);
            ulonglong2 p0 = sh[0], p1 = sh[1], p2 = sh[2], p3 = sh[3];
            unsigned long long h[8] = {p0.x, p0.y, p1.x, p1.y, p2.x, p2.y, p3.x, p3.y};

            float4 a = acur[k];
            float m0 = a.x > 0.f ? 1.f : 0.f;
            float m1 = a.y > 0.f ? 1.f : 0.f;
            float m2 = a.z > 0.f ? 1.f : 0.f;
            float m3 = a.w > 0.f ? 1.f : 0.f;
            cnt[0] += m0; cnt[1] += m1; cnt[2] += m2; cnt[3] += m3;
            unsigned long long mm[4] = {pack2(m0, m0), pack2(m1, m1),
                                        pack2(m2, m2), pack2(m3, m3)};
            #pragma unroll
            for (int q = 0; q < CPT; q++)
                #pragma unroll
                for (int c = 0; c < 8; c++)
                    w[q][c] = fma2(mm[q], h[c], w[q][c]);
        }
    }

    // Epilogue: per-thread quad / dH / s contributions
    float quad_t = 0.f, s_t = 0.f;
    float dh_t[C_DIM];
    #pragma unroll
    for (int c = 0; c < C_DIM; c++) dh_t[c] = 0.f;

    #pragma unroll
    for (int q = 0; q < CPT; q++) {
        const float* Hj = H + (size_t)(col0 + q) * C_DIM;
        float hj[C_DIM];
        const float4* Hj4 = (const float4*)Hj;
        #pragma unroll
        for (int c4 = 0; c4 < 4; c4++) {
            float4 v = __ldg(Hj4 + c4);
            hj[4*c4+0] = v.x; hj[4*c4+1] = v.y; hj[4*c4+2] = v.z; hj[4*c4+3] = v.w;
        }
        #pragma unroll
        for (int c = 0; c < 8; c++) {
            float lo, hi; unpack2(w[q][c], lo, hi);
            quad_t += hj[2*c] * lo + hj[2*c+1] * hi;
        }
        #pragma unroll
        for (int c = 0; c < C_DIM; c++) dh_t[c] += cnt[q] * hj[c];
        s_t += cnt[q];
    }

    // Warp-level reduction of 18 values
    #pragma unroll
    for (int off = 16; off > 0; off >>= 1) {
        quad_t += __shfl_xor_sync(0xffffffffu, quad_t, off);
        s_t    += __shfl_xor_sync(0xffffffffu, s_t, off);
        #pragma unroll
        for (int c = 0; c < C_DIM; c++)
            dh_t[c] += __shfl_xor_sync(0xffffffffu, dh_t[c], off);
    }

    __shared__ float sred[TPB / 32][18];
    const int warp = threadIdx.x >> 5, lane = threadIdx.x & 31;
    if (lane == 0) {
        sred[warp][0] = quad_t;
        sred[warp][1] = s_t;
        #pragma unroll
        for (int c = 0; c < C_DIM; c++) sred[warp][2 + c] = dh_t[c];
    }
    __syncthreads();
    if (threadIdx.x < 18) {
        float v = 0.f;
        #pragma unroll
        for (int wd = 0; wd < TPB / 32; wd++) v += sred[wd][threadIdx.x];
        g_part[blockIdx.y * GX + blockIdx.x][threadIdx.x] = v;
    }
}

// Final reduction + scalar loss. 18 warps: warp w reduces component w.
__global__ void modmax_final(float* __restrict__ out) {
    __shared__ float comp[18];
    const int warp = threadIdx.x >> 5, lane = threadIdx.x & 31;
    if (warp < 18) {
        float v = 0.f;
        for (int i = lane; i < NBLK; i += 32) v += g_part[i][warp];
        #pragma unroll
        for (int off = 16; off > 0; off >>= 1)
            v += __shfl_xor_sync(0xffffffffu, v, off);
        if (lane == 0) comp[warp] = v;
    }
    __syncthreads();
    if (threadIdx.x == 0) {
        float quad = comp[0], s = comp[1];
        float dd = 0.f;
        #pragma unroll
        for (int c = 0; c < C_DIM; c++) dd += comp[2 + c] * comp[2 + c];
        out[0] = (quad - dd / s) / s;
    }
}

extern "C" void kernel_launch(void* const* d_in, const int* in_sizes, int n_in,
                              void* d_out, int out_size) {
    const float* H = (const float*)d_in[0];
    const float* A = (const float*)d_in[1];
    // Defensive: pick by size (H is N*C, A is N*N)
    if (in_sizes[0] != N_NODES * C_DIM) { const float* t = H; H = A; A = t; }

    dim3 grid(GX, GY);
    modmax_main<<<grid, TPB>>>(A, H);
    modmax_final<<<1, 576>>>((float*)d_out);
}

// round 4
// speedup vs baseline: 1.1914x; 1.1914x over previous
#include <cuda_runtime.h>
#include <cstdint>
#include <cstddef>

// Problem constants
constexpr int N_NODES = 8192;
constexpr int C_DIM   = 16;

// Tiling
constexpr int TPB = 256;                 // threads per block
constexpr int CPT = 4;                   // columns per thread (one LDG.128)
constexpr int CPB = TPB * CPT;           // 1024 columns per block
constexpr int RPB = 64;                  // rows per block
constexpr int GX  = N_NODES / CPB;       // 8
constexpr int GY  = N_NODES / RPB;       // 128
constexpr int NBLK = GX * GY;            // 1024
constexpr int PD  = 4;                   // prefetch distance (batches of 4 rows)
constexpr int NB  = RPB / 4;             // 16 batches

// partials layout per block: [0]=quad, [1]=s, [2..17]=dH[16]
__device__ float g_part[NBLK][18];
__device__ unsigned int g_done = 0;      // wraps back to 0 via atomicInc

__device__ __forceinline__ unsigned long long pack2(float x, float y) {
    unsigned long long r;
    asm("mov.b64 %0, {%1, %2};" : "=l"(r) : "f"(x), "f"(y));
    return r;
}
__device__ __forceinline__ void unpack2(unsigned long long v, float& x, float& y) {
    asm("mov.b64 {%0, %1}, %2;" : "=f"(x), "=f"(y) : "l"(v));
}
// packed fp32x2 FMA (Blackwell sm_10x): d = a*b + c on two lanes
__device__ __forceinline__ unsigned long long fma2(unsigned long long a,
                                                   unsigned long long b,
                                                   unsigned long long c) {
    unsigned long long d;
    asm("fma.rn.f32x2 %0, %1, %2, %3;" : "=l"(d) : "l"(a), "l"(b), "l"(c));
    return d;
}

__global__ void __launch_bounds__(TPB, 1)
modmax_fused(const float* __restrict__ A, const float* __restrict__ H,
             float* __restrict__ out) {
    __shared__ __align__(16) float sH[RPB * C_DIM];   // 4 KB: H rows for this chunk

    const int tid  = threadIdx.x;
    const int bid  = blockIdx.y * GX + blockIdx.x;
    const int row0 = blockIdx.y * RPB;
    const int col0 = blockIdx.x * CPB + tid * CPT;

    // Stage H[row0 : row0+RPB][0:16] into smem (64*16 floats = 256 float4)
    {
        const float4* src = (const float4*)(H + (size_t)row0 * C_DIM);
        ((float4*)sH)[tid] = src[tid];
    }
    __syncthreads();

    // Accumulators: w[q][c] = sum_i adj[i][j_q] * H[i][2c:2c+2]
    unsigned long long w[CPT][8];
    #pragma unroll
    for (int q = 0; q < CPT; q++)
        #pragma unroll
        for (int c = 0; c < 8; c++) w[q][c] = 0ULL;
    float cnt[CPT] = {0.f, 0.f, 0.f, 0.f};

    const float4* Aeff = (const float4*)(A + (size_t)row0 * N_NODES + col0);
    const size_t rowStride4 = N_NODES / 4;

    // Deep software pipeline: PD batches of 4 rows (16 LDG.128 in flight)
    float4 abuf[PD][4];
    #pragma unroll
    for (int p = 0; p < PD; p++)
        #pragma unroll
        for (int k = 0; k < 4; k++)
            abuf[p][k] = __ldg(Aeff + (size_t)(p * 4 + k) * rowStride4);

    #pragma unroll 1
    for (int it = 0; it < NB; it += PD) {
        #pragma unroll
        for (int p = 0; p < PD; p++) {
            const int b = it + p;                 // batch index
            float4 acur[4];
            #pragma unroll
            for (int k = 0; k < 4; k++) acur[k] = abuf[p][k];
            if (b + PD < NB) {
                #pragma unroll
                for (int k = 0; k < 4; k++)
                    abuf[p][k] = __ldg(Aeff + (size_t)((b + PD) * 4 + k) * rowStride4);
            }
            #pragma unroll
            for (int k = 0; k < 4; k++) {
                const int ii = b * 4 + k;
                // H[ii] as 8 packed f32x2 (broadcast LDS.128 x4, conflict-free)
                const ulonglong2* sh = (const ulonglong2*)(sH + ii * C_DIM);
                ulonglong2 p0 = sh[0], p1 = sh[1], p2 = sh[2], p3 = sh[3];
                unsigned long long h[8] = {p0.x, p0.y, p1.x, p1.y,
                                           p2.x, p2.y, p3.x, p3.y};

                float4 a = acur[k];
                float m0 = a.x > 0.f ? 1.f : 0.f;
                float m1 = a.y > 0.f ? 1.f : 0.f;
                float m2 = a.z > 0.f ? 1.f : 0.f;
                float m3 = a.w > 0.f ? 1.f : 0.f;
                cnt[0] += m0; cnt[1] += m1; cnt[2] += m2; cnt[3] += m3;
                unsigned long long mm[4] = {pack2(m0, m0), pack2(m1, m1),
                                            pack2(m2, m2), pack2(m3, m3)};
                #pragma unroll
                for (int q = 0; q < CPT; q++)
                    #pragma unroll
                    for (int c = 0; c < 8; c++)
                        w[q][c] = fma2(mm[q], h[c], w[q][c]);
            }
        }
    }

    // Epilogue: per-thread quad / dH / s contributions
    float quad_t = 0.f, s_t = 0.f;
    float dh_t[C_DIM];
    #pragma unroll
    for (int c = 0; c < C_DIM; c++) dh_t[c] = 0.f;

    #pragma unroll
    for (int q = 0; q < CPT; q++) {
        const float4* Hj4 = (const float4*)(H + (size_t)(col0 + q) * C_DIM);
        float hj[C_DIM];
        #pragma unroll
        for (int c4 = 0; c4 < 4; c4++) {
            float4 v = __ldg(Hj4 + c4);
            hj[4*c4+0] = v.x; hj[4*c4+1] = v.y; hj[4*c4+2] = v.z; hj[4*c4+3] = v.w;
        }
        #pragma unroll
        for (int c = 0; c < 8; c++) {
            float lo, hi; unpack2(w[q][c], lo, hi);
            quad_t += hj[2*c] * lo + hj[2*c+1] * hi;
        }
        #pragma unroll
        for (int c = 0; c < C_DIM; c++) dh_t[c] += cnt[q] * hj[c];
        s_t += cnt[q];
    }

    // Warp-level reduction of 18 values
    #pragma unroll
    for (int off = 16; off > 0; off >>= 1) {
        quad_t += __shfl_xor_sync(0xffffffffu, quad_t, off);
        s_t    += __shfl_xor_sync(0xffffffffu, s_t, off);
        #pragma unroll
        for (int c = 0; c < C_DIM; c++)
            dh_t[c] += __shfl_xor_sync(0xffffffffu, dh_t[c], off);
    }

    __shared__ float sred[TPB / 32][18];
    const int warp = tid >> 5, lane = tid & 31;
    if (lane == 0) {
        sred[warp][0] = quad_t;
        sred[warp][1] = s_t;
        #pragma unroll
        for (int c = 0; c < C_DIM; c++) sred[warp][2 + c] = dh_t[c];
    }
    __syncthreads();
    if (tid < 18) {
        float v = 0.f;
        #pragma unroll
        for (int wd = 0; wd < TPB / 32; wd++) v += sred[wd][tid];
        g_part[bid][tid] = v;
    }

    // ---- fused final reduction: last block to finish does it ----
    __threadfence();                      // make g_part[bid] globally visible
    __syncthreads();
    __shared__ bool isLast;
    if (tid == 0) {
        unsigned old = atomicInc(&g_done, NBLK - 1);   // wraps to 0 -> self-reset
        isLast = (old == NBLK - 1);
    }
    __syncthreads();
    if (!isLast) return;

    __threadfence();                      // acquire: other blocks' partials
    __shared__ float comp[18];
    // warp w reduces components w, w+8, w+16
    for (int c = warp; c < 18; c += TPB / 32) {
        float v = 0.f;
        #pragma unroll
        for (int i = 0; i < NBLK / 32; i++) v += g_part[lane + 32 * i][c];
        #pragma unroll
        for (int off = 16; off > 0; off >>= 1)
            v += __shfl_xor_sync(0xffffffffu, v, off);
        if (lane == 0) comp[c] = v;
    }
    __syncthreads();
    if (tid == 0) {
        float quad = comp[0], s = comp[1];
        float dd = 0.f;
        #pragma unroll
        for (int c = 0; c < C_DIM; c++) dd += comp[2 + c] * comp[2 + c];
        out[0] = (quad - dd / s) / s;
    }
}

extern "C" void kernel_launch(void* const* d_in, const int* in_sizes, int n_in,
                              void* d_out, int out_size) {
    const float* H = (const float*)d_in[0];
    const float* A = (const float*)d_in[1];
    // Defensive: pick by size (H is N*C, A is N*N)
    if (in_sizes[0] != N_NODES * C_DIM) { const float* t = H; H = A; A = t; }

    dim3 grid(GX, GY);
    modmax_fused<<<grid, TPB>>>(A, H, (float*)d_out);
}

// round 6
// speedup vs baseline: 1.3297x; 1.1161x over previous
#include <cuda_runtime.h>
#include <cstdint>
#include <cstddef>

// Problem constants
constexpr int N_NODES = 8192;
constexpr int C_DIM   = 16;

// Tiling
constexpr int TPB = 256;                 // threads per block
constexpr int CPT = 2;                   // columns per thread (one LDG.64)
constexpr int CPB = TPB * CPT;           // 512 columns per block
constexpr int RPB = 64;                  // rows per block
constexpr int GX  = N_NODES / CPB;       // 16
constexpr int GY  = N_NODES / RPB;       // 128
constexpr int NBLK = GX * GY;            // 2048
constexpr int PD  = 4;                   // prefetch distance (batches of 4 rows)
constexpr int NB  = RPB / 4;             // 16 batches

// partials layout per block: [0]=quad, [1]=s, [2..17]=dH[16]
__device__ float g_part[NBLK][18];
__device__ unsigned int g_done = 0;      // wraps back to 0 via atomicInc

__device__ __forceinline__ unsigned long long pack2(float x, float y) {
    unsigned long long r;
    asm("mov.b64 %0, {%1, %2};" : "=l"(r) : "f"(x), "f"(y));
    return r;
}
__device__ __forceinline__ void unpack2(unsigned long long v, float& x, float& y) {
    asm("mov.b64 {%0, %1}, %2;" : "=f"(x), "=f"(y) : "l"(v));
}
// packed fp32x2 FMA (Blackwell sm_10x): d = a*b + c on two lanes
__device__ __forceinline__ unsigned long long fma2(unsigned long long a,
                                                   unsigned long long b,
                                                   unsigned long long c) {
    unsigned long long d;
    asm("fma.rn.f32x2 %0, %1, %2, %3;" : "=l"(d) : "l"(a), "l"(b), "l"(c));
    return d;
}

__global__ void __launch_bounds__(TPB, 2)
modmax_fused(const float* __restrict__ A, const float* __restrict__ H,
             float* __restrict__ out) {
    __shared__ __align__(16) float sH[RPB * C_DIM];   // 4 KB: H rows for this chunk

    const int tid  = threadIdx.x;
    const int bid  = blockIdx.y * GX + blockIdx.x;
    const int row0 = blockIdx.y * RPB;
    const int col0 = blockIdx.x * CPB + tid * CPT;

    // Stage H[row0 : row0+RPB][0:16] into smem (64*16 floats = 256 float4)
    {
        const float4* src = (const float4*)(H + (size_t)row0 * C_DIM);
        ((float4*)sH)[tid] = src[tid];
    }
    __syncthreads();

    // Accumulators: w[q][c] = sum_i adj[i][j_q] * H[i][2c:2c+2]
    unsigned long long w[CPT][8];
    #pragma unroll
    for (int q = 0; q < CPT; q++)
        #pragma unroll
        for (int c = 0; c < 8; c++) w[q][c] = 0ULL;
    float cnt[CPT] = {0.f, 0.f};

    const float2* Aeff = (const float2*)(A + (size_t)row0 * N_NODES + col0);
    const size_t rowStride2 = N_NODES / 2;

    // Deep software pipeline: PD batches of 4 rows (16 LDG.64 in flight)
    float2 abuf[PD][4];
    #pragma unroll
    for (int p = 0; p < PD; p++)
        #pragma unroll
        for (int k = 0; k < 4; k++)
            abuf[p][k] = __ldg(Aeff + (size_t)(p * 4 + k) * rowStride2);

    #pragma unroll 1
    for (int it = 0; it < NB; it += PD) {
        #pragma unroll
        for (int p = 0; p < PD; p++) {
            const int b = it + p;                 // batch index
            float2 acur[4];
            #pragma unroll
            for (int k = 0; k < 4; k++) acur[k] = abuf[p][k];
            if (b + PD < NB) {
                #pragma unroll
                for (int k = 0; k < 4; k++)
                    abuf[p][k] = __ldg(Aeff + (size_t)((b + PD) * 4 + k) * rowStride2);
            }
            #pragma unroll
            for (int k = 0; k < 4; k++) {
                const int ii = b * 4 + k;
                // H[ii] as 8 packed f32x2 (broadcast LDS.128 x4, conflict-free)
                const ulonglong2* sh = (const ulonglong2*)(sH + ii * C_DIM);
                ulonglong2 p0 = sh[0], p1 = sh[1], p2 = sh[2], p3 = sh[3];
                unsigned long long h[8] = {p0.x, p0.y, p1.x, p1.y,
                                           p2.x, p2.y, p3.x, p3.y};

                float2 a = acur[k];
                float m0 = a.x > 0.f ? 1.f : 0.f;
                float m1 = a.y > 0.f ? 1.f : 0.f;
                cnt[0] += m0; cnt[1] += m1;
                unsigned long long mm[2] = {pack2(m0, m0), pack2(m1, m1)};
                #pragma unroll
                for (int q = 0; q < CPT; q++)
                    #pragma unroll
                    for (int c = 0; c < 8; c++)
                        w[q][c] = fma2(mm[q], h[c], w[q][c]);
            }
        }
    }

    // Epilogue: per-thread quad / dH / s contributions
    float quad_t = 0.f, s_t = 0.f;
    float dh_t[C_DIM];
    #pragma unroll
    for (int c = 0; c < C_DIM; c++) dh_t[c] = 0.f;

    #pragma unroll
    for (int q = 0; q < CPT; q++) {
        const float4* Hj4 = (const float4*)(H + (size_t)(col0 + q) * C_DIM);
        float hj[C_DIM];
        #pragma unroll
        for (int c4 = 0; c4 < 4; c4++) {
            float4 v = __ldg(Hj4 + c4);
            hj[4*c4+0] = v.x; hj[4*c4+1] = v.y; hj[4*c4+2] = v.z; hj[4*c4+3] = v.w;
        }
        #pragma unroll
        for (int c = 0; c < 8; c++) {
            float lo, hi; unpack2(w[q][c], lo, hi);
            quad_t += hj[2*c] * lo + hj[2*c+1] * hi;
        }
        #pragma unroll
        for (int c = 0; c < C_DIM; c++) dh_t[c] += cnt[q] * hj[c];
        s_t += cnt[q];
    }

    // Warp-level reduction of 18 values
    #pragma unroll
    for (int off = 16; off > 0; off >>= 1) {
        quad_t += __shfl_xor_sync(0xffffffffu, quad_t, off);
        s_t    += __shfl_xor_sync(0xffffffffu, s_t, off);
        #pragma unroll
        for (int c = 0; c < C_DIM; c++)
            dh_t[c] += __shfl_xor_sync(0xffffffffu, dh_t[c], off);
    }

    __shared__ float sred[TPB / 32][18];
    const int warp = tid >> 5, lane = tid & 31;
    if (lane == 0) {
        sred[warp][0] = quad_t;
        sred[warp][1] = s_t;
        #pragma unroll
        for (int c = 0; c < C_DIM; c++) sred[warp][2 + c] = dh_t[c];
    }
    __syncthreads();
    if (tid < 18) {
        float v = 0.f;
        #pragma unroll
        for (int wd = 0; wd < TPB / 32; wd++) v += sred[wd][tid];
        g_part[bid][tid] = v;
    }

    // ---- fused final reduction: last block to finish does it ----
    __threadfence();                      // make g_part[bid] globally visible
    __syncthreads();
    __shared__ bool isLast;
    if (tid == 0) {
        unsigned old = atomicInc(&g_done, NBLK - 1);   // wraps to 0 -> self-reset
        isLast = (old == NBLK - 1);
    }
    __syncthreads();
    if (!isLast) return;

    __threadfence();                      // acquire: other blocks' partials
    __shared__ float comp[18];
    // 8 warps: warp w reduces components w, w+8, (w+16)
    for (int c = warp; c < 18; c += TPB / 32) {
        float v = 0.f;
        #pragma unroll
        for (int i = 0; i < NBLK / 32; i++) v += g_part[lane + 32 * i][c];
        #pragma unroll
        for (int off = 16; off > 0; off >>= 1)
            v += __shfl_xor_sync(0xffffffffu, v, off);
        if (lane == 0) comp[c] = v;
    }
    __syncthreads();
    if (tid == 0) {
        float quad = comp[0], s = comp[1];
        float dd = 0.f;
        #pragma unroll
        for (int c = 0; c < C_DIM; c++) dd += comp[2 + c] * comp[2 + c];
        out[0] = (quad - dd / s) / s;
    }
}

extern "C" void kernel_launch(void* const* d_in, const int* in_sizes, int n_in,
                              void* d_out, int out_size) {
    const float* H = (const float*)d_in[0];
    const float* A = (const float*)d_in[1];
    // Defensive: pick by size (H is N*C, A is N*N)
    if (in_sizes[0] != N_NODES * C_DIM) { const float* t = H; H = A; A = t; }

    dim3 grid(GX, GY);
    modmax_fused<<<grid, TPB>>>(A, H, (float*)d_out);
}